// round 15
// baseline (speedup 1.0000x reference)
#include <cuda_runtime.h>
#include <math.h>

// ---------------- problem constants ----------------
#define Bn     4
#define Pn     12000
#define Nn     32
#define PNn    (Pn*Nn)            // 384000
#define TOTn   (Bn*PNn)           // 1536000
#define HH     282
#define OH1    278
#define PH1    139
#define OH2    136
#define PH2    68
#define FCIN   (16*PH2*PH2)       // 73984
#define NPILT  (Bn*Pn)            // 48000 pillar entries per half
#define OSZ1   (OH1*OH1)          // 77284
#define MOMB   256                // pfn_mom blocks per half
#define WTN    (2*25*64*64)       // transposed conv1 weights
#define P1TOT  (Bn*64*PH1*PH1)    // pool1 elements
#define P1GRID 592
#define C2SZ   ((size_t)Bn*16*OH2*OH2)

typedef unsigned long long ull;

// ---------------- packed f32x2 helpers ----------------
__device__ __forceinline__ ull pk2(float lo, float hi) {
    ull r;
    asm("mov.b64 %0, {%1, %2};" : "=l"(r) : "f"(lo), "f"(hi));
    return r;
}
__device__ __forceinline__ void upk2(ull v, float& lo, float& hi) {
    asm("mov.b64 {%0, %1}, %2;" : "=f"(lo), "=f"(hi) : "l"(v));
}
__device__ __forceinline__ void ffma2(ull& d, ull a, ull b) {
    asm("fma.rn.f32x2 %0, %1, %2, %0;" : "+l"(d) : "l"(a), "l"(b));
}

// ---------------- scratch (static device memory; no allocs) ----------------
// g_conv1 holds ACCUMULATED conv sums only (no bias). Zero at the start of
// every call: module-load zero-init on first call; tail kernel re-zeroes after.
__device__ float  g_conv1 [(size_t)Bn*OSZ1*64];       //  79.1 MB, interleaved [b][cell][oc]
__device__ float  g_pool1 [(size_t)Bn*64*PH1*PH1];    //  19.8 MB, planar, RAW pooled max
__device__ float  g_conv2p[2][C2SZ];                  // per-ci-half partial conv2 (no bias)
__device__ float  g_pool2 [(size_t)Bn*16*PH2*PH2];    // RAW pooled max of conv2 acc
__device__ float  g_featT [(size_t)2*NPILT*64];       // pillar-major PFN features
__device__ int    g_cxy   [2*NPILT];                  // packed (cy<<16)|cx per pillar
__device__ float  g_wc1T  [WTN];                      // wT[half][tap][ci64][oc64]
__device__ double g_mompart[2][MOMB][44];             // per-block moment partials
__device__ double g_c1stats[128];
__device__ double g_c2stats[32];
__device__ float  g_weff  [2][512];
__device__ float  g_beff  [2][64];
__device__ float  g_ab1   [128];
__device__ float  g_ab2   [32];
__device__ float  g_h     [128];

// ---------------- PFN moments (y=0,1; float4) + conv1 weight transpose (y=2) ----------------
__global__ void pfn_mom_kernel(const float* __restrict__ xs, const float* __restrict__ xm,
                               const float* __restrict__ wc1) {
    if (blockIdx.y == 2) {
        // wT[half][tap][ci][oc] = wc1[oc][half*64+ci][tap]
        for (int idx = blockIdx.x * 256 + threadIdx.x; idx < WTN; idx += MOMB * 256) {
            int half = idx / (25 * 4096);
            int r    = idx % (25 * 4096);
            int tap  = r / 4096;
            int r2   = r & 4095;
            int ci   = r2 >> 6, oc = r2 & 63;
            g_wc1T[idx] = wc1[((size_t)oc * 128 + half * 64 + ci) * 25 + tap];
        }
        return;
    }
    const float* x = blockIdx.y ? xm : xs;
    float a[44];
#pragma unroll
    for (int k = 0; k < 44; k++) a[k] = 0.f;

    const int Q = PNn / 4;
    for (int i4 = blockIdx.x * blockDim.x + threadIdx.x; i4 < TOTn / 4; i4 += MOMB * blockDim.x) {
        int b = i4 / Q, r4 = i4 % Q;
        const float4* p = (const float4*)(x + (size_t)b * 8 * PNn) + r4;
        float4 v[8];
#pragma unroll
        for (int c = 0; c < 8; c++) v[c] = p[(size_t)c * Q];
#pragma unroll
        for (int c = 0; c < 8; c++) a[c] += (v[c].x + v[c].y) + (v[c].z + v[c].w);
        int k = 8;
#pragma unroll
        for (int c = 0; c < 8; c++)
#pragma unroll
            for (int c2 = c; c2 < 8; c2++) {
                a[k] = fmaf(v[c].x, v[c2].x, a[k]);
                a[k] = fmaf(v[c].y, v[c2].y, a[k]);
                a[k] = fmaf(v[c].z, v[c2].z, a[k]);
                a[k] = fmaf(v[c].w, v[c2].w, a[k]);
                k++;
            }
    }

    __shared__ double sm[44];
    if (threadIdx.x < 44) sm[threadIdx.x] = 0.0;
    __syncthreads();
    int lane = threadIdx.x & 31;
#pragma unroll
    for (int k = 0; k < 44; k++) {
        float s = a[k];
#pragma unroll
        for (int o = 16; o > 0; o >>= 1) s += __shfl_down_sync(0xffffffffu, s, o);
        if (lane == 0) atomicAdd(&sm[k], (double)s);
    }
    __syncthreads();
    if (threadIdx.x < 44) g_mompart[blockIdx.y][blockIdx.x][threadIdx.x] = sm[threadIdx.x];
}

// Reduce moment partials + fold BN into effective PFN weight/bias.
// Also zeroes the conv stats accumulators (block 0: c1, block 1: c2).
__global__ void pfn_fin_kernel(const float* __restrict__ w_s, const float* __restrict__ b_s,
                               const float* __restrict__ g_s, const float* __restrict__ be_s,
                               const float* __restrict__ w_m, const float* __restrict__ b_m,
                               const float* __restrict__ g_m, const float* __restrict__ be_m) {
    int half = blockIdx.x;
    int o = threadIdx.x;
    if (half == 0) {
        if (o < 64) { g_c1stats[o] = 0.0; g_c1stats[64 + o] = 0.0; }
    } else {
        if (o < 16) { g_c2stats[o] = 0.0; g_c2stats[16 + o] = 0.0; }
    }

    __shared__ double sm[44];
    if (o < 44) {
        double s = 0.0;
        for (int bk = 0; bk < MOMB; bk++) s += g_mompart[half][bk][o];
        sm[o] = s;
    }
    __syncthreads();
    if (o >= 64) return;

    const float* w    = half ? w_m  : w_s;
    const float* bias = half ? b_m  : b_s;
    const float* g    = half ? g_m  : g_s;
    const float* be   = half ? be_m : be_s;
    const double invNT = 1.0 / (double)TOTn;

    double wv[8];
#pragma unroll
    for (int c = 0; c < 8; c++) wv[c] = (double)w[o * 8 + c];
    double bo = (double)bias[o];

    double mu = bo;
#pragma unroll
    for (int c = 0; c < 8; c++) mu += wv[c] * (sm[c] * invNT);

    double quad = 0.0;
    int k = 8;
#pragma unroll
    for (int c = 0; c < 8; c++)
#pragma unroll
        for (int c2 = c; c2 < 8; c2++) {
            double Mv = sm[k] * invNT;
            k++;
            double t = wv[c] * wv[c2] * Mv;
            quad += (c == c2) ? t : (2.0 * t);
        }

    double ey2 = bo * bo + 2.0 * bo * (mu - bo) + quad;
    double var = ey2 - mu * mu;
    double alpha = (double)g[o] / sqrt(var + 1e-5);
    double beta  = (double)be[o] - mu * alpha;
#pragma unroll
    for (int c = 0; c < 8; c++) g_weff[half][o * 8 + c] = (float)(alpha * wv[c]);
    g_beff[half][o] = (float)(alpha * bo + beta);
}

// PFN pass 2, both halves (blockIdx.y = half). Warp = TWO pillars, 16 lanes
// each, lane covers 2 points; 4 shfl per o serve both pillars.
__global__ void pfn_max_kernel(const float* __restrict__ xs, const float* __restrict__ xm) {
    __shared__ float swf[512];
    __shared__ float sbf[64];
    int half = blockIdx.y;
    const float* x = half ? xm : xs;
    int tid = threadIdx.x;
    for (int i = tid; i < 512; i += 256) swf[i] = g_weff[half][i];
    if (tid < 64) sbf[tid] = g_beff[half][tid];
    __syncthreads();

    int warp = (blockIdx.x * 256 + tid) >> 5;
    int lane = tid & 31;
    int pp = warp * 2 + (lane >> 4);
    if (pp >= Bn * Pn) return;
    int b = pp / Pn, p = pp % Pn;
    int pe = half * NPILT + pp;
    int l = lane & 15;

    const float* xb = x + ((size_t)b * 8 * Pn + p) * Nn;
    float x1[8], x2[8];
#pragma unroll
    for (int c = 0; c < 8; c++) {
        x1[c] = xb[(size_t)c * PNn + l];
        x2[c] = xb[(size_t)c * PNn + l + 16];
    }

    if (l == 0) {
        int gx = (int)floorf((x1[0] + 22.0f) / 0.16f);
        int gy = (int)floorf((x1[1] + 22.0f) / 0.16f);
        g_cxy[pe] = (gx << 16) | gy;
    }

    float r0 = 0.f, r1 = 0.f, r2 = 0.f, r3 = 0.f;
    for (int o = 0; o < 64; o++) {
        float d1 = sbf[o], d2 = d1;
#pragma unroll
        for (int c = 0; c < 8; c++) {
            float w = swf[o * 8 + c];
            d1 = fmaf(w, x1[c], d1);
            d2 = fmaf(w, x2[c], d2);
        }
        float y = fmaxf(d1, d2);
#pragma unroll
        for (int m = 8; m > 0; m >>= 1) y = fmaxf(y, __shfl_xor_sync(0xffffffffu, y, m));
        y = fmaxf(y, 0.f);
        if ((o & 15) == l) {
            int sel = o >> 4;
            if (sel == 0) r0 = y;
            else if (sel == 1) r1 = y;
            else if (sel == 2) r2 = y;
            else r3 = y;
        }
    }
    float* fp = g_featT + (size_t)pe * 64;
    fp[l] = r0; fp[l + 16] = r1; fp[l + 32] = r2; fp[l + 48] = r3;
}

// ---------------- sparse scatter conv1 (ci-split, oc-quad, v4 atomics) ----------------
// block = (chunk of 480 pillars, oc-group of 16, ci-half, pfn-half), 128 threads.
// thread t<100 = (tap, oc-quad of 4): 32 ci x 4 oc = 64 ffma2 per pillar with
// 8 LDS.128 per pillar (8:1 smem balance) and ONE red.global.add.v4.f32.
// SC_PB = 16: 30 barriers per block (halved vs R13).
#define SC_CHUNKS 25
#define SC_PPC    480
#define SC_PB     16
__global__ __launch_bounds__(128) void sconv1_kernel() {
    __shared__ __align__(16) float sf[2][SC_PB][32];
    __shared__ int   scell[2][SC_PB];
    int t      = threadIdx.x;
    int chunk  = blockIdx.x;              // 0..99
    int ocg    = blockIdx.y;              // 0..3 -> oc base 16*ocg
    int cihalf = blockIdx.z & 1;
    int half   = blockIdx.z >> 1;
    int b      = chunk / SC_CHUNKS;
    int sub    = chunk % SC_CHUNKS;
    int pbase  = half * NPILT + b * Pn + sub * SC_PPC;

    int quad = t & 3;
    int tap  = t >> 2;
    int tapc = tap > 24 ? 24 : tap;
    int dy   = tapc / 5, dx = tapc - dy * 5;
    int oc0  = ocg * 16 + quad * 4;
    bool active = (t < 100);

    // weights from transposed layout: w2[j][p] = (w[ci=2p], w[ci=2p+1]) for oc0+j
    ull w2[4][16];
    {
        const float* wt = g_wc1T + (((size_t)half * 25 + tapc) * 64 + cihalf * 32) * 64 + oc0;
#pragma unroll
        for (int p = 0; p < 16; p++) {
            float4 fa = *(const float4*)(wt + (size_t)(2 * p) * 64);
            float4 fb = *(const float4*)(wt + (size_t)(2 * p + 1) * 64);
            w2[0][p] = pk2(fa.x, fb.x);
            w2[1][p] = pk2(fa.y, fb.y);
            w2[2][p] = pk2(fa.z, fb.z);
            w2[3][p] = pk2(fa.w, fb.w);
        }
    }
    float* outp = g_conv1 + (size_t)b * OSZ1 * 64 + oc0;

    int lpi = t >> 3, lq = t & 7;         // loader: 128 threads, one float4 each
    float4 pf; int cpf = 0;

    // prologue: stage group 0 (only this block's 32-ci half)
    ((float4*)sf[0][lpi])[lq] =
        *(const float4*)(g_featT + (size_t)(pbase + lpi) * 64 + cihalf * 32 + lq * 4);
    if (t < SC_PB) scell[0][t] = g_cxy[pbase + t];
    __syncthreads();

    for (int gp = 0; gp < SC_PPC / SC_PB; gp++) {
        int cur = gp & 1;

        if (gp + 1 < SC_PPC / SC_PB) {
            int p0 = pbase + (gp + 1) * SC_PB;
            pf = *(const float4*)(g_featT + (size_t)(p0 + lpi) * 64 + cihalf * 32 + lq * 4);
            if (t < SC_PB) cpf = g_cxy[p0 + t];
        }

#pragma unroll 1
        for (int pi = 0; pi < SC_PB; pi++) {
            const ulonglong2* fv = (const ulonglong2*)sf[cur][pi];
            ull a0 = 0ull, a1 = 0ull, a2 = 0ull, a3 = 0ull;
#pragma unroll
            for (int k = 0; k < 8; k++) {
                ulonglong2 u = fv[k];
                ffma2(a0, u.x, w2[0][2 * k]);     ffma2(a1, u.x, w2[1][2 * k]);
                ffma2(a2, u.x, w2[2][2 * k]);     ffma2(a3, u.x, w2[3][2 * k]);
                ffma2(a0, u.y, w2[0][2 * k + 1]); ffma2(a1, u.y, w2[1][2 * k + 1]);
                ffma2(a2, u.y, w2[2][2 * k + 1]); ffma2(a3, u.y, w2[3][2 * k + 1]);
            }
            float lo, hi;
            float y0, y1, y2, y3;
            upk2(a0, lo, hi); y0 = lo + hi;
            upk2(a1, lo, hi); y1 = lo + hi;
            upk2(a2, lo, hi); y2 = lo + hi;
            upk2(a3, lo, hi); y3 = lo + hi;

            int cxy = scell[cur][pi];
            int oy = (cxy >> 16) - dy;
            int ox = (cxy & 0xFFFF) - dx;
            if (active && (unsigned)oy < (unsigned)OH1 && (unsigned)ox < (unsigned)OH1) {
                float* p = outp + (size_t)(oy * OH1 + ox) * 64;
                asm volatile("red.global.add.v4.f32 [%0], {%1, %2, %3, %4};"
                             :: "l"(p), "f"(y0), "f"(y1), "f"(y2), "f"(y3) : "memory");
            }
        }

        if (gp + 1 < SC_PPC / SC_PB) {
            int nb = 1 - cur;
            ((float4*)sf[nb][lpi])[lq] = pf;
            if (t < SC_PB) scell[nb][t] = cpf;
        }
        __syncthreads();
    }
}

// pool1 FUSED with c1stats: windows tile OH1 exactly; stores RAW window max
// (affine+relu commute with max since alpha>0; applied in conv2 staging) and
// accumulates per-oc sum/sumsq of the raw values.
__global__ void pool1_kernel() {
    int tid = threadIdx.x;
    int t0 = blockIdx.x * 256 + tid;
    int oc = t0 & 63;                       // stride P1GRID*256 is a multiple of 64
    float s = 0.f, sq = 0.f;
    for (int t = t0; t < P1TOT; t += P1GRID * 256) {
        int cell = t >> 6;
        int j = cell % PH1; int tmp = cell / PH1;
        int i = tmp % PH1; int b = tmp / PH1;
        const float* base = g_conv1 + ((size_t)b * OSZ1 + (size_t)(2 * i) * OH1 + 2 * j) * 64 + oc;
        float v0 = base[0];
        float v1 = base[64];
        float v2 = base[(size_t)OH1 * 64];
        float v3 = base[(size_t)(OH1 + 1) * 64];
        s  += (v0 + v1) + (v2 + v3);
        sq += (v0 * v0 + v1 * v1) + (v2 * v2 + v3 * v3);
        g_pool1[(((size_t)b * 64 + oc) * PH1 + i) * PH1 + j] = fmaxf(fmaxf(v0, v1), fmaxf(v2, v3));
    }
    __shared__ float rs[256], rq[256];
    rs[tid] = s; rq[tid] = sq;
    __syncthreads();
    if (tid < 64) {
        double S = (double)rs[tid] + (double)rs[tid + 64] + (double)rs[tid + 128] + (double)rs[tid + 192];
        double Q = (double)rq[tid] + (double)rq[tid + 64] + (double)rq[tid + 128] + (double)rq[tid + 192];
        atomicAdd(&g_c1stats[oc], S);
        atomicAdd(&g_c1stats[64 + oc], Q);
    }
}

// BN finalize -> alpha/beta (stats over raw acc; conv bias folded):
//   mean = m_acc + b;  var = q_acc + 2 b m_acc + b^2 - mean^2
//   ab[C+c] = alpha*b + beta (downstream reads raw acc).
__global__ void bn_fin_kernel(int which,
                              const float* __restrict__ g, const float* __restrict__ be,
                              const float* __restrict__ bias, double invN) {
    int C = (which == 1) ? 64 : 16;
    const double* stats = (which == 1) ? g_c1stats : g_c2stats;
    float* ab           = (which == 1) ? g_ab1     : g_ab2;
    int c = threadIdx.x;
    if (c >= C) return;
    double bb   = (double)bias[c];
    double macc = stats[c] * invN;
    double q    = stats[C + c] * invN;
    double mean = macc + bb;
    double var  = q + 2.0 * bb * macc + bb * bb - mean * mean;
    double alpha = (double)g[c] / sqrt(var + 1e-5);
    double beta  = (double)be[c] - mean * alpha;
    ab[c]     = (float)alpha;
    ab[C + c] = (float)(alpha * bb + beta);
}

// ---------------- conv2: 4x4, 64->16, tile 32x32, ci-SPLIT x2 ----------------
// Each block handles 32 of the 64 input channels and writes its partial sums
// (no bias) to its own buffer g_conv2p[cih]. Staging applies conv1's BN
// affine + ReLU to the RAW pooled values. Stats moved to pool2.
__global__ __launch_bounds__(256) void conv2_kernel(const float* __restrict__ wc2) {
    __shared__ float sp[35][36];
    __shared__ float sw[128];
    int tid = threadIdx.x;
    int z = blockIdx.z;
    int b = z >> 2, ocg = (z >> 1) & 1, cih = z & 1;
    int oy  = blockIdx.y * 32, ox = blockIdx.x * 32;

    float acc[8][4];
#pragma unroll
    for (int i = 0; i < 8; i++)
#pragma unroll
        for (int j = 0; j < 4; j++) acc[i][j] = 0.f;

    const float* cb = g_pool1 + ((size_t)b * 64 + cih * 32) * PH1 * PH1;
    int r0 = (tid >> 4) * 2, c0 = (tid & 15) * 2;

    for (int ci = 0; ci < 32; ci++) {
        int cig = cih * 32 + ci;
        __syncthreads();
        const float* src = cb + (size_t)ci * PH1 * PH1;
        float a1 = g_ab1[cig], b1 = g_ab1[64 + cig];
        for (int i = tid; i < 35 * 35; i += 256) {
            int r = i / 35, c = i % 35;
            int gy = oy + r, gx = ox + c;
            sp[r][c] = (gy < PH1 && gx < PH1)
                     ? fmaxf(fmaf(a1, src[gy * PH1 + gx], b1), 0.f) : 0.f;
        }
        if (tid < 128) sw[tid] = wc2[((ocg * 8 + (tid >> 4)) * 64 + cig) * 16 + (tid & 15)];
        __syncthreads();

        float pr[5][5];
#pragma unroll
        for (int i = 0; i < 5; i++)
#pragma unroll
            for (int j = 0; j < 5; j++) pr[i][j] = sp[r0 + i][c0 + j];

#pragma unroll
        for (int oc = 0; oc < 8; oc++)
#pragma unroll
            for (int ky = 0; ky < 4; ky++)
#pragma unroll
                for (int kx = 0; kx < 4; kx++) {
                    float wv = sw[oc * 16 + ky * 4 + kx];
#pragma unroll
                    for (int iy = 0; iy < 2; iy++)
#pragma unroll
                        for (int ix = 0; ix < 2; ix++)
                            acc[oc][iy * 2 + ix] = fmaf(pr[ky + iy][kx + ix], wv, acc[oc][iy * 2 + ix]);
                }
    }

#pragma unroll
    for (int oc = 0; oc < 8; oc++) {
#pragma unroll
        for (int iy = 0; iy < 2; iy++)
#pragma unroll
            for (int ix = 0; ix < 2; ix++) {
                int ro = oy + r0 + iy, co = ox + c0 + ix;
                if (ro < OH2 && co < OH2)
                    g_conv2p[cih][(((size_t)b * 16 + ocg * 8 + oc) * OH2 + ro) * OH2 + co]
                        = acc[oc][iy * 2 + ix];
            }
    }
}

// pool2 FUSED with c2stats: sums the two ci-half partials, accumulates per-
// channel sum/sumsq of the raw (bias-free) values, stores RAW window max.
__global__ void pool2_kernel() {
    __shared__ double ss[16], sqq[16];
    int tid = threadIdx.x;
    if (tid < 16) { ss[tid] = 0.0; sqq[tid] = 0.0; }
    __syncthreads();

    int t = blockIdx.x * 256 + tid;
    int j = t % PH2; int tmp = t / PH2;
    int i = tmp % PH2; tmp /= PH2;
    int c = tmp % 16;  int b = tmp / 16;
    size_t base = (((size_t)b * 16 + c) * OH2 + 2 * i) * OH2 + 2 * j;
    float v0 = g_conv2p[0][base]            + g_conv2p[1][base];
    float v1 = g_conv2p[0][base + 1]        + g_conv2p[1][base + 1];
    float v2 = g_conv2p[0][base + OH2]      + g_conv2p[1][base + OH2];
    float v3 = g_conv2p[0][base + OH2 + 1]  + g_conv2p[1][base + OH2 + 1];
    float s  = (v0 + v1) + (v2 + v3);
    float sq = (v0 * v0 + v1 * v1) + (v2 * v2 + v3 * v3);
    g_pool2[t] = fmaxf(fmaxf(v0, v1), fmaxf(v2, v3));

    atomicAdd(&ss[c], (double)s);
    atomicAdd(&sqq[c], (double)sq);
    __syncthreads();
    if (tid < 16) {
        atomicAdd(&g_c2stats[tid], ss[tid]);
        atomicAdd(&g_c2stats[16 + tid], sqq[tid]);
    }
}

// ---------------- fc1: applies conv2's BN affine + ReLU per element ----------------
__global__ void fc1_kernel(const float* __restrict__ w, const float* __restrict__ bias) {
    int j = blockIdx.x, b = blockIdx.y, tid = threadIdx.x;
    const float* x  = g_pool2 + (size_t)b * FCIN;
    const float* wr = w + (size_t)j * FCIN;
    float s = 0.f;
    for (int i = tid; i < FCIN; i += 256) {
        int c = i / (PH2 * PH2);
        float xv = fmaxf(fmaf(g_ab2[c], x[i], g_ab2[16 + c]), 0.f);
        s = fmaf(xv, wr[i], s);
    }
    __shared__ float red[256];
    red[tid] = s;
    __syncthreads();
    for (int k = 128; k > 0; k >>= 1) {
        if (tid < k) red[tid] += red[tid + k];
        __syncthreads();
    }
    if (tid == 0) g_h[b * 32 + j] = red[0] + bias[j];
}

// ---------------- head ----------------
__global__ void head_kernel(const float* __restrict__ gfc, const float* __restrict__ befc,
                            const float* __restrict__ wout, const float* __restrict__ bout,
                            float* __restrict__ out) {
    __shared__ float hn[4][32];
    int t = threadIdx.x;
    if (t < 32) {
        float h0 = g_h[t], h1 = g_h[32 + t], h2 = g_h[64 + t], h3 = g_h[96 + t];
        float m = 0.25f * (h0 + h1 + h2 + h3);
        float d0 = h0 - m, d1 = h1 - m, d2 = h2 - m, d3 = h3 - m;
        float v = 0.25f * (d0 * d0 + d1 * d1 + d2 * d2 + d3 * d3);
        float inv = rsqrtf(v + 1e-5f);
        float gg = gfc[t], bb = befc[t];
        hn[0][t] = tanhf(fmaf(d0 * inv, gg, bb));
        hn[1][t] = tanhf(fmaf(d1 * inv, gg, bb));
        hn[2][t] = tanhf(fmaf(d2 * inv, gg, bb));
        hn[3][t] = tanhf(fmaf(d3 * inv, gg, bb));
    }
    __syncthreads();
    if (t < 12) {
        int b = t / 3, k = t % 3;
        float s = bout[k];
#pragma unroll
        for (int j = 0; j < 32; j++) s = fmaf(hn[b][j], wout[k * 32 + j], s);
        out[b * 3 + k] = s;
    }
}

// tail: streaming re-zero of conv1 accumulator for the next call / graph replay
__global__ void conv1_zero_kernel() {
    size_t t = (size_t)blockIdx.x * 256 + threadIdx.x;
    const size_t n4 = ((size_t)Bn * OSZ1 * 64) / 4;
    if (t < n4) ((float4*)g_conv1)[t] = make_float4(0.f, 0.f, 0.f, 0.f);
}

// ---------------- launch ----------------
extern "C" void kernel_launch(void* const* d_in, const int* in_sizes, int n_in,
                              void* d_out, int out_size) {
    const float* sweep   = (const float*)d_in[0];
    const float* map_pts = (const float*)d_in[1];
    const float* w_pfn_s = (const float*)d_in[2];
    const float* b_pfn_s = (const float*)d_in[3];
    const float* g_pfn_s = (const float*)d_in[4];
    const float* be_pfn_s= (const float*)d_in[5];
    const float* w_pfn_m = (const float*)d_in[6];
    const float* b_pfn_m = (const float*)d_in[7];
    const float* g_pfn_m = (const float*)d_in[8];
    const float* be_pfn_m= (const float*)d_in[9];
    const float* w_c1    = (const float*)d_in[10];
    const float* b_c1    = (const float*)d_in[11];
    const float* g_c1    = (const float*)d_in[12];
    const float* be_c1   = (const float*)d_in[13];
    const float* w_c2    = (const float*)d_in[14];
    const float* b_c2    = (const float*)d_in[15];
    const float* g_c2    = (const float*)d_in[16];
    const float* be_c2   = (const float*)d_in[17];
    const float* w_fc1   = (const float*)d_in[18];
    const float* b_fc1   = (const float*)d_in[19];
    const float* g_fc1   = (const float*)d_in[20];
    const float* be_fc1  = (const float*)d_in[21];
    const float* w_out   = (const float*)d_in[22];
    const float* b_out   = (const float*)d_in[23];
    float* out = (float*)d_out;

    // g_conv1 is zero here: module-load init on first call, tail kernel after.
    pfn_mom_kernel<<<dim3(MOMB, 3), 256>>>(sweep, map_pts, w_c1);          // 0 (+wT)
    pfn_fin_kernel<<<2, 64>>>(w_pfn_s, b_pfn_s, g_pfn_s, be_pfn_s,
                              w_pfn_m, b_pfn_m, g_pfn_m, be_pfn_m);        // 1
    pfn_max_kernel<<<dim3((Bn * Pn) / 16, 2), 256>>>(sweep, map_pts);      // 2

    sconv1_kernel<<<dim3(Bn * SC_CHUNKS, 4, 4), 128>>>();                  // 3 <- profiled slot

    pool1_kernel<<<P1GRID, 256>>>();                                       // 4 (pool + c1 stats)
    bn_fin_kernel<<<1, 64>>>(1, g_c1, be_c1, b_c1, 1.0 / ((double)Bn * OSZ1));

    conv2_kernel<<<dim3(5, 5, 16), 256>>>(w_c2);                           // ci-split x2
    pool2_kernel<<<(Bn * 16 * PH2 * PH2) / 256, 256>>>();                  // pool + c2 stats
    bn_fin_kernel<<<1, 32>>>(2, g_c2, be_c2, b_c2, 1.0 / ((double)Bn * OH2 * OH2));

    fc1_kernel<<<dim3(32, 4), 256>>>(w_fc1, b_fc1);
    head_kernel<<<1, 64>>>(g_fc1, be_fc1, w_out, b_out, out);

    // restore invariant: conv1 accumulator zero for next call/replay
    {
        size_t n4 = ((size_t)Bn * OSZ1 * 64) / 4;
        conv1_zero_kernel<<<(int)((n4 + 255) / 256), 256>>>();
    }
}

// round 16
// speedup vs baseline: 1.0335x; 1.0335x over previous
#include <cuda_runtime.h>
#include <math.h>

// ---------------- problem constants ----------------
#define Bn     4
#define Pn     12000
#define Nn     32
#define PNn    (Pn*Nn)            // 384000
#define TOTn   (Bn*PNn)           // 1536000
#define HH     282
#define OH1    278
#define PH1    139
#define OH2    136
#define PH2    68
#define FCIN   (16*PH2*PH2)       // 73984
#define NPILT  (Bn*Pn)            // 48000 pillar entries per half
#define OSZ1   (OH1*OH1)          // 77284
#define MOMB   256                // pfn_mom blocks per half
#define WTN    (2*25*64*64)       // transposed conv1 weights
#define P1TOT  (Bn*64*PH1*PH1)    // pool1 elements
#define P1GRID 592
#define C2SZ   ((size_t)Bn*16*OH2*OH2)
#define P2WIN  (PH2*PH2)          // 4624 pool2 windows per (b,c)

typedef unsigned long long ull;

// ---------------- packed f32x2 helpers ----------------
__device__ __forceinline__ ull pk2(float lo, float hi) {
    ull r;
    asm("mov.b64 %0, {%1, %2};" : "=l"(r) : "f"(lo), "f"(hi));
    return r;
}
__device__ __forceinline__ void upk2(ull v, float& lo, float& hi) {
    asm("mov.b64 {%0, %1}, %2;" : "=f"(lo), "=f"(hi) : "l"(v));
}
__device__ __forceinline__ void ffma2(ull& d, ull a, ull b) {
    asm("fma.rn.f32x2 %0, %1, %2, %0;" : "+l"(d) : "l"(a), "l"(b));
}

// ---------------- scratch (static device memory; no allocs) ----------------
// g_conv1 holds ACCUMULATED conv sums only (no bias). Zero at the start of
// every call: module-load zero-init on first call; tail kernel re-zeroes after.
__device__ float  g_conv1 [(size_t)Bn*OSZ1*64];       //  79.1 MB, interleaved [b][cell][oc]
__device__ float  g_pool1 [(size_t)Bn*64*PH1*PH1];    //  19.8 MB, planar, RAW pooled max
__device__ float  g_conv2p[2][C2SZ];                  // per-ci-half partial conv2 (no bias)
__device__ float  g_pool2 [(size_t)Bn*16*PH2*PH2];    // RAW pooled max of conv2 acc
__device__ float  g_featT [(size_t)2*NPILT*64];       // pillar-major PFN features
__device__ int    g_cxy   [2*NPILT];                  // packed (cy<<16)|cx per pillar
__device__ float  g_wc1T  [WTN];                      // wT[half][tap][ci64][oc64]
__device__ double g_mompart[2][MOMB][44];             // per-block moment partials
__device__ double g_c1stats[128];
__device__ double g_c2stats[32];
__device__ float  g_weff  [2][512];
__device__ float  g_beff  [2][64];
__device__ float  g_ab1   [128];
__device__ float  g_ab2   [32];
__device__ float  g_h     [128];

// ---------------- PFN moments (y=0,1; float4) + conv1 weight transpose (y=2) ----------------
__global__ void pfn_mom_kernel(const float* __restrict__ xs, const float* __restrict__ xm,
                               const float* __restrict__ wc1) {
    if (blockIdx.y == 2) {
        // wT[half][tap][ci][oc] = wc1[oc][half*64+ci][tap]
        for (int idx = blockIdx.x * 256 + threadIdx.x; idx < WTN; idx += MOMB * 256) {
            int half = idx / (25 * 4096);
            int r    = idx % (25 * 4096);
            int tap  = r / 4096;
            int r2   = r & 4095;
            int ci   = r2 >> 6, oc = r2 & 63;
            g_wc1T[idx] = wc1[((size_t)oc * 128 + half * 64 + ci) * 25 + tap];
        }
        return;
    }
    const float* x = blockIdx.y ? xm : xs;
    float a[44];
#pragma unroll
    for (int k = 0; k < 44; k++) a[k] = 0.f;

    const int Q = PNn / 4;
    for (int i4 = blockIdx.x * blockDim.x + threadIdx.x; i4 < TOTn / 4; i4 += MOMB * blockDim.x) {
        int b = i4 / Q, r4 = i4 % Q;
        const float4* p = (const float4*)(x + (size_t)b * 8 * PNn) + r4;
        float4 v[8];
#pragma unroll
        for (int c = 0; c < 8; c++) v[c] = p[(size_t)c * Q];
#pragma unroll
        for (int c = 0; c < 8; c++) a[c] += (v[c].x + v[c].y) + (v[c].z + v[c].w);
        int k = 8;
#pragma unroll
        for (int c = 0; c < 8; c++)
#pragma unroll
            for (int c2 = c; c2 < 8; c2++) {
                a[k] = fmaf(v[c].x, v[c2].x, a[k]);
                a[k] = fmaf(v[c].y, v[c2].y, a[k]);
                a[k] = fmaf(v[c].z, v[c2].z, a[k]);
                a[k] = fmaf(v[c].w, v[c2].w, a[k]);
                k++;
            }
    }

    __shared__ double sm[44];
    if (threadIdx.x < 44) sm[threadIdx.x] = 0.0;
    __syncthreads();
    int lane = threadIdx.x & 31;
#pragma unroll
    for (int k = 0; k < 44; k++) {
        float s = a[k];
#pragma unroll
        for (int o = 16; o > 0; o >>= 1) s += __shfl_down_sync(0xffffffffu, s, o);
        if (lane == 0) atomicAdd(&sm[k], (double)s);
    }
    __syncthreads();
    if (threadIdx.x < 44) g_mompart[blockIdx.y][blockIdx.x][threadIdx.x] = sm[threadIdx.x];
}

// Reduce moment partials + fold BN into effective PFN weight/bias.
// Also zeroes the conv stats accumulators (block 0: c1, block 1: c2).
__global__ void pfn_fin_kernel(const float* __restrict__ w_s, const float* __restrict__ b_s,
                               const float* __restrict__ g_s, const float* __restrict__ be_s,
                               const float* __restrict__ w_m, const float* __restrict__ b_m,
                               const float* __restrict__ g_m, const float* __restrict__ be_m) {
    int half = blockIdx.x;
    int o = threadIdx.x;
    if (half == 0) {
        if (o < 64) { g_c1stats[o] = 0.0; g_c1stats[64 + o] = 0.0; }
    } else {
        if (o < 16) { g_c2stats[o] = 0.0; g_c2stats[16 + o] = 0.0; }
    }

    __shared__ double sm[44];
    if (o < 44) {
        double s = 0.0;
        for (int bk = 0; bk < MOMB; bk++) s += g_mompart[half][bk][o];
        sm[o] = s;
    }
    __syncthreads();
    if (o >= 64) return;

    const float* w    = half ? w_m  : w_s;
    const float* bias = half ? b_m  : b_s;
    const float* g    = half ? g_m  : g_s;
    const float* be   = half ? be_m : be_s;
    const double invNT = 1.0 / (double)TOTn;

    double wv[8];
#pragma unroll
    for (int c = 0; c < 8; c++) wv[c] = (double)w[o * 8 + c];
    double bo = (double)bias[o];

    double mu = bo;
#pragma unroll
    for (int c = 0; c < 8; c++) mu += wv[c] * (sm[c] * invNT);

    double quad = 0.0;
    int k = 8;
#pragma unroll
    for (int c = 0; c < 8; c++)
#pragma unroll
        for (int c2 = c; c2 < 8; c2++) {
            double Mv = sm[k] * invNT;
            k++;
            double t = wv[c] * wv[c2] * Mv;
            quad += (c == c2) ? t : (2.0 * t);
        }

    double ey2 = bo * bo + 2.0 * bo * (mu - bo) + quad;
    double var = ey2 - mu * mu;
    double alpha = (double)g[o] / sqrt(var + 1e-5);
    double beta  = (double)be[o] - mu * alpha;
#pragma unroll
    for (int c = 0; c < 8; c++) g_weff[half][o * 8 + c] = (float)(alpha * wv[c]);
    g_beff[half][o] = (float)(alpha * bo + beta);
}

// PFN pass 2, both halves (blockIdx.y = half). Warp = TWO pillars, 16 lanes
// each, lane covers 2 points; 4 shfl per o serve both pillars.
__global__ void pfn_max_kernel(const float* __restrict__ xs, const float* __restrict__ xm) {
    __shared__ float swf[512];
    __shared__ float sbf[64];
    int half = blockIdx.y;
    const float* x = half ? xm : xs;
    int tid = threadIdx.x;
    for (int i = tid; i < 512; i += 256) swf[i] = g_weff[half][i];
    if (tid < 64) sbf[tid] = g_beff[half][tid];
    __syncthreads();

    int warp = (blockIdx.x * 256 + tid) >> 5;
    int lane = tid & 31;
    int pp = warp * 2 + (lane >> 4);
    if (pp >= Bn * Pn) return;
    int b = pp / Pn, p = pp % Pn;
    int pe = half * NPILT + pp;
    int l = lane & 15;

    const float* xb = x + ((size_t)b * 8 * Pn + p) * Nn;
    float x1[8], x2[8];
#pragma unroll
    for (int c = 0; c < 8; c++) {
        x1[c] = xb[(size_t)c * PNn + l];
        x2[c] = xb[(size_t)c * PNn + l + 16];
    }

    if (l == 0) {
        int gx = (int)floorf((x1[0] + 22.0f) / 0.16f);
        int gy = (int)floorf((x1[1] + 22.0f) / 0.16f);
        g_cxy[pe] = (gx << 16) | gy;
    }

    float r0 = 0.f, r1 = 0.f, r2 = 0.f, r3 = 0.f;
    for (int o = 0; o < 64; o++) {
        float d1 = sbf[o], d2 = d1;
#pragma unroll
        for (int c = 0; c < 8; c++) {
            float w = swf[o * 8 + c];
            d1 = fmaf(w, x1[c], d1);
            d2 = fmaf(w, x2[c], d2);
        }
        float y = fmaxf(d1, d2);
#pragma unroll
        for (int m = 8; m > 0; m >>= 1) y = fmaxf(y, __shfl_xor_sync(0xffffffffu, y, m));
        y = fmaxf(y, 0.f);
        if ((o & 15) == l) {
            int sel = o >> 4;
            if (sel == 0) r0 = y;
            else if (sel == 1) r1 = y;
            else if (sel == 2) r2 = y;
            else r3 = y;
        }
    }
    float* fp = g_featT + (size_t)pe * 64;
    fp[l] = r0; fp[l + 16] = r1; fp[l + 32] = r2; fp[l + 48] = r3;
}

// ---------------- sparse scatter conv1 (ci-split, oc-quad, v4 atomics) ----------------
// block = (chunk of 480 pillars, oc-group of 16, ci-half, pfn-half), 128 threads.
// thread t<100 = (tap, oc-quad of 4): 32 ci x 4 oc = 64 ffma2 per pillar with
// 8 LDS.128 per pillar (8:1 smem balance) and ONE red.global.add.v4.f32.
// SC_PB = 16: 30 barriers per block.
#define SC_CHUNKS 25
#define SC_PPC    480
#define SC_PB     16
__global__ __launch_bounds__(128) void sconv1_kernel() {
    __shared__ __align__(16) float sf[2][SC_PB][32];
    __shared__ int   scell[2][SC_PB];
    int t      = threadIdx.x;
    int chunk  = blockIdx.x;              // 0..99
    int ocg    = blockIdx.y;              // 0..3 -> oc base 16*ocg
    int cihalf = blockIdx.z & 1;
    int half   = blockIdx.z >> 1;
    int b      = chunk / SC_CHUNKS;
    int sub    = chunk % SC_CHUNKS;
    int pbase  = half * NPILT + b * Pn + sub * SC_PPC;

    int quad = t & 3;
    int tap  = t >> 2;
    int tapc = tap > 24 ? 24 : tap;
    int dy   = tapc / 5, dx = tapc - dy * 5;
    int oc0  = ocg * 16 + quad * 4;
    bool active = (t < 100);

    // weights from transposed layout: w2[j][p] = (w[ci=2p], w[ci=2p+1]) for oc0+j
    ull w2[4][16];
    {
        const float* wt = g_wc1T + (((size_t)half * 25 + tapc) * 64 + cihalf * 32) * 64 + oc0;
#pragma unroll
        for (int p = 0; p < 16; p++) {
            float4 fa = *(const float4*)(wt + (size_t)(2 * p) * 64);
            float4 fb = *(const float4*)(wt + (size_t)(2 * p + 1) * 64);
            w2[0][p] = pk2(fa.x, fb.x);
            w2[1][p] = pk2(fa.y, fb.y);
            w2[2][p] = pk2(fa.z, fb.z);
            w2[3][p] = pk2(fa.w, fb.w);
        }
    }
    float* outp = g_conv1 + (size_t)b * OSZ1 * 64 + oc0;

    int lpi = t >> 3, lq = t & 7;         // loader: 128 threads, one float4 each
    float4 pf; int cpf = 0;

    // prologue: stage group 0 (only this block's 32-ci half)
    ((float4*)sf[0][lpi])[lq] =
        *(const float4*)(g_featT + (size_t)(pbase + lpi) * 64 + cihalf * 32 + lq * 4);
    if (t < SC_PB) scell[0][t] = g_cxy[pbase + t];
    __syncthreads();

    for (int gp = 0; gp < SC_PPC / SC_PB; gp++) {
        int cur = gp & 1;

        if (gp + 1 < SC_PPC / SC_PB) {
            int p0 = pbase + (gp + 1) * SC_PB;
            pf = *(const float4*)(g_featT + (size_t)(p0 + lpi) * 64 + cihalf * 32 + lq * 4);
            if (t < SC_PB) cpf = g_cxy[p0 + t];
        }

#pragma unroll 1
        for (int pi = 0; pi < SC_PB; pi++) {
            const ulonglong2* fv = (const ulonglong2*)sf[cur][pi];
            ull a0 = 0ull, a1 = 0ull, a2 = 0ull, a3 = 0ull;
#pragma unroll
            for (int k = 0; k < 8; k++) {
                ulonglong2 u = fv[k];
                ffma2(a0, u.x, w2[0][2 * k]);     ffma2(a1, u.x, w2[1][2 * k]);
                ffma2(a2, u.x, w2[2][2 * k]);     ffma2(a3, u.x, w2[3][2 * k]);
                ffma2(a0, u.y, w2[0][2 * k + 1]); ffma2(a1, u.y, w2[1][2 * k + 1]);
                ffma2(a2, u.y, w2[2][2 * k + 1]); ffma2(a3, u.y, w2[3][2 * k + 1]);
            }
            float lo, hi;
            float y0, y1, y2, y3;
            upk2(a0, lo, hi); y0 = lo + hi;
            upk2(a1, lo, hi); y1 = lo + hi;
            upk2(a2, lo, hi); y2 = lo + hi;
            upk2(a3, lo, hi); y3 = lo + hi;

            int cxy = scell[cur][pi];
            int oy = (cxy >> 16) - dy;
            int ox = (cxy & 0xFFFF) - dx;
            if (active && (unsigned)oy < (unsigned)OH1 && (unsigned)ox < (unsigned)OH1) {
                float* p = outp + (size_t)(oy * OH1 + ox) * 64;
                asm volatile("red.global.add.v4.f32 [%0], {%1, %2, %3, %4};"
                             :: "l"(p), "f"(y0), "f"(y1), "f"(y2), "f"(y3) : "memory");
            }
        }

        if (gp + 1 < SC_PPC / SC_PB) {
            int nb = 1 - cur;
            ((float4*)sf[nb][lpi])[lq] = pf;
            if (t < SC_PB) scell[nb][t] = cpf;
        }
        __syncthreads();
    }
}

// pool1 FUSED with c1stats: windows tile OH1 exactly; stores RAW window max
// (affine+relu commute with max since alpha>0; applied in conv2 staging) and
// accumulates per-oc sum/sumsq of the raw values.
__global__ void pool1_kernel() {
    int tid = threadIdx.x;
    int t0 = blockIdx.x * 256 + tid;
    int oc = t0 & 63;                       // stride P1GRID*256 is a multiple of 64
    float s = 0.f, sq = 0.f;
    for (int t = t0; t < P1TOT; t += P1GRID * 256) {
        int cell = t >> 6;
        int j = cell % PH1; int tmp = cell / PH1;
        int i = tmp % PH1; int b = tmp / PH1;
        const float* base = g_conv1 + ((size_t)b * OSZ1 + (size_t)(2 * i) * OH1 + 2 * j) * 64 + oc;
        float v0 = base[0];
        float v1 = base[64];
        float v2 = base[(size_t)OH1 * 64];
        float v3 = base[(size_t)(OH1 + 1) * 64];
        s  += (v0 + v1) + (v2 + v3);
        sq += (v0 * v0 + v1 * v1) + (v2 * v2 + v3 * v3);
        g_pool1[(((size_t)b * 64 + oc) * PH1 + i) * PH1 + j] = fmaxf(fmaxf(v0, v1), fmaxf(v2, v3));
    }
    __shared__ float rs[256], rq[256];
    rs[tid] = s; rq[tid] = sq;
    __syncthreads();
    if (tid < 64) {
        double S = (double)rs[tid] + (double)rs[tid + 64] + (double)rs[tid + 128] + (double)rs[tid + 192];
        double Q = (double)rq[tid] + (double)rq[tid + 64] + (double)rq[tid + 128] + (double)rq[tid + 192];
        atomicAdd(&g_c1stats[oc], S);
        atomicAdd(&g_c1stats[64 + oc], Q);
    }
}

// BN finalize -> alpha/beta (stats over raw acc; conv bias folded):
//   mean = m_acc + b;  var = q_acc + 2 b m_acc + b^2 - mean^2
//   ab[C+c] = alpha*b + beta (downstream reads raw acc).
__global__ void bn_fin_kernel(int which,
                              const float* __restrict__ g, const float* __restrict__ be,
                              const float* __restrict__ bias, double invN) {
    int C = (which == 1) ? 64 : 16;
    const double* stats = (which == 1) ? g_c1stats : g_c2stats;
    float* ab           = (which == 1) ? g_ab1     : g_ab2;
    int c = threadIdx.x;
    if (c >= C) return;
    double bb   = (double)bias[c];
    double macc = stats[c] * invN;
    double q    = stats[C + c] * invN;
    double mean = macc + bb;
    double var  = q + 2.0 * bb * macc + bb * bb - mean * mean;
    double alpha = (double)g[c] / sqrt(var + 1e-5);
    double beta  = (double)be[c] - mean * alpha;
    ab[c]     = (float)alpha;
    ab[C + c] = (float)(alpha * bb + beta);
}

// ---------------- conv2: 4x4, 64->16, tile 32x32, ci-SPLIT x2 ----------------
// Each block handles 32 of the 64 input channels and writes its partial sums
// (no bias) to its own buffer g_conv2p[cih]. Staging applies conv1's BN
// affine + ReLU to the RAW pooled values. Stats moved to pool2.
__global__ __launch_bounds__(256) void conv2_kernel(const float* __restrict__ wc2) {
    __shared__ float sp[35][36];
    __shared__ float sw[128];
    int tid = threadIdx.x;
    int z = blockIdx.z;
    int b = z >> 2, ocg = (z >> 1) & 1, cih = z & 1;
    int oy  = blockIdx.y * 32, ox = blockIdx.x * 32;

    float acc[8][4];
#pragma unroll
    for (int i = 0; i < 8; i++)
#pragma unroll
        for (int j = 0; j < 4; j++) acc[i][j] = 0.f;

    const float* cb = g_pool1 + ((size_t)b * 64 + cih * 32) * PH1 * PH1;
    int r0 = (tid >> 4) * 2, c0 = (tid & 15) * 2;

    for (int ci = 0; ci < 32; ci++) {
        int cig = cih * 32 + ci;
        __syncthreads();
        const float* src = cb + (size_t)ci * PH1 * PH1;
        float a1 = g_ab1[cig], b1 = g_ab1[64 + cig];
        for (int i = tid; i < 35 * 35; i += 256) {
            int r = i / 35, c = i % 35;
            int gy = oy + r, gx = ox + c;
            sp[r][c] = (gy < PH1 && gx < PH1)
                     ? fmaxf(fmaf(a1, src[gy * PH1 + gx], b1), 0.f) : 0.f;
        }
        if (tid < 128) sw[tid] = wc2[((ocg * 8 + (tid >> 4)) * 64 + cig) * 16 + (tid & 15)];
        __syncthreads();

        float pr[5][5];
#pragma unroll
        for (int i = 0; i < 5; i++)
#pragma unroll
            for (int j = 0; j < 5; j++) pr[i][j] = sp[r0 + i][c0 + j];

#pragma unroll
        for (int oc = 0; oc < 8; oc++)
#pragma unroll
            for (int ky = 0; ky < 4; ky++)
#pragma unroll
                for (int kx = 0; kx < 4; kx++) {
                    float wv = sw[oc * 16 + ky * 4 + kx];
#pragma unroll
                    for (int iy = 0; iy < 2; iy++)
#pragma unroll
                        for (int ix = 0; ix < 2; ix++)
                            acc[oc][iy * 2 + ix] = fmaf(pr[ky + iy][kx + ix], wv, acc[oc][iy * 2 + ix]);
                }
    }

#pragma unroll
    for (int oc = 0; oc < 8; oc++) {
#pragma unroll
        for (int iy = 0; iy < 2; iy++)
#pragma unroll
            for (int ix = 0; ix < 2; ix++) {
                int ro = oy + r0 + iy, co = ox + c0 + ix;
                if (ro < OH2 && co < OH2)
                    g_conv2p[cih][(((size_t)b * 16 + ocg * 8 + oc) * OH2 + ro) * OH2 + co]
                        = acc[oc][iy * 2 + ix];
            }
    }
}

// pool2 FUSED with c2stats. Block = one (b, channel) plane -> channel is
// block-uniform: tree-reduce in smem, TWO global atomics per block (the R15
// version serialized 256 same-address shared-double atomics per block).
__global__ void pool2_kernel() {
    int tid = threadIdx.x;
    int bc = blockIdx.x;                  // b*16 + c, 0..63
    int c = bc & 15;
    float s = 0.f, sq = 0.f;
    for (int w = tid; w < P2WIN; w += 256) {
        int i = w / PH2, j = w % PH2;
        size_t base = ((size_t)bc * OH2 + 2 * i) * OH2 + 2 * j;
        float v0 = g_conv2p[0][base]           + g_conv2p[1][base];
        float v1 = g_conv2p[0][base + 1]       + g_conv2p[1][base + 1];
        float v2 = g_conv2p[0][base + OH2]     + g_conv2p[1][base + OH2];
        float v3 = g_conv2p[0][base + OH2 + 1] + g_conv2p[1][base + OH2 + 1];
        s  += (v0 + v1) + (v2 + v3);
        sq += (v0 * v0 + v1 * v1) + (v2 * v2 + v3 * v3);
        g_pool2[(size_t)bc * P2WIN + w] = fmaxf(fmaxf(v0, v1), fmaxf(v2, v3));
    }
    __shared__ float rs[256], rq[256];
    rs[tid] = s; rq[tid] = sq;
    __syncthreads();
    for (int k = 128; k > 0; k >>= 1) {
        if (tid < k) { rs[tid] += rs[tid + k]; rq[tid] += rq[tid + k]; }
        __syncthreads();
    }
    if (tid == 0) {
        atomicAdd(&g_c2stats[c], (double)rs[0]);
        atomicAdd(&g_c2stats[16 + c], (double)rq[0]);
    }
}

// ---------------- fc1: applies conv2's BN affine + ReLU per element ----------------
__global__ void fc1_kernel(const float* __restrict__ w, const float* __restrict__ bias) {
    int j = blockIdx.x, b = blockIdx.y, tid = threadIdx.x;
    const float* x  = g_pool2 + (size_t)b * FCIN;
    const float* wr = w + (size_t)j * FCIN;
    float s = 0.f;
    for (int i = tid; i < FCIN; i += 256) {
        int c = i / (PH2 * PH2);
        float xv = fmaxf(fmaf(g_ab2[c], x[i], g_ab2[16 + c]), 0.f);
        s = fmaf(xv, wr[i], s);
    }
    __shared__ float red[256];
    red[tid] = s;
    __syncthreads();
    for (int k = 128; k > 0; k >>= 1) {
        if (tid < k) red[tid] += red[tid + k];
        __syncthreads();
    }
    if (tid == 0) g_h[b * 32 + j] = red[0] + bias[j];
}

// ---------------- head ----------------
__global__ void head_kernel(const float* __restrict__ gfc, const float* __restrict__ befc,
                            const float* __restrict__ wout, const float* __restrict__ bout,
                            float* __restrict__ out) {
    __shared__ float hn[4][32];
    int t = threadIdx.x;
    if (t < 32) {
        float h0 = g_h[t], h1 = g_h[32 + t], h2 = g_h[64 + t], h3 = g_h[96 + t];
        float m = 0.25f * (h0 + h1 + h2 + h3);
        float d0 = h0 - m, d1 = h1 - m, d2 = h2 - m, d3 = h3 - m;
        float v = 0.25f * (d0 * d0 + d1 * d1 + d2 * d2 + d3 * d3);
        float inv = rsqrtf(v + 1e-5f);
        float gg = gfc[t], bb = befc[t];
        hn[0][t] = tanhf(fmaf(d0 * inv, gg, bb));
        hn[1][t] = tanhf(fmaf(d1 * inv, gg, bb));
        hn[2][t] = tanhf(fmaf(d2 * inv, gg, bb));
        hn[3][t] = tanhf(fmaf(d3 * inv, gg, bb));
    }
    __syncthreads();
    if (t < 12) {
        int b = t / 3, k = t % 3;
        float s = bout[k];
#pragma unroll
        for (int j = 0; j < 32; j++) s = fmaf(hn[b][j], wout[k * 32 + j], s);
        out[b * 3 + k] = s;
    }
}

// tail: streaming re-zero of conv1 accumulator for the next call / graph replay
__global__ void conv1_zero_kernel() {
    size_t t = (size_t)blockIdx.x * 256 + threadIdx.x;
    const size_t n4 = ((size_t)Bn * OSZ1 * 64) / 4;
    if (t < n4) ((float4*)g_conv1)[t] = make_float4(0.f, 0.f, 0.f, 0.f);
}

// ---------------- launch ----------------
extern "C" void kernel_launch(void* const* d_in, const int* in_sizes, int n_in,
                              void* d_out, int out_size) {
    const float* sweep   = (const float*)d_in[0];
    const float* map_pts = (const float*)d_in[1];
    const float* w_pfn_s = (const float*)d_in[2];
    const float* b_pfn_s = (const float*)d_in[3];
    const float* g_pfn_s = (const float*)d_in[4];
    const float* be_pfn_s= (const float*)d_in[5];
    const float* w_pfn_m = (const float*)d_in[6];
    const float* b_pfn_m = (const float*)d_in[7];
    const float* g_pfn_m = (const float*)d_in[8];
    const float* be_pfn_m= (const float*)d_in[9];
    const float* w_c1    = (const float*)d_in[10];
    const float* b_c1    = (const float*)d_in[11];
    const float* g_c1    = (const float*)d_in[12];
    const float* be_c1   = (const float*)d_in[13];
    const float* w_c2    = (const float*)d_in[14];
    const float* b_c2    = (const float*)d_in[15];
    const float* g_c2    = (const float*)d_in[16];
    const float* be_c2   = (const float*)d_in[17];
    const float* w_fc1   = (const float*)d_in[18];
    const float* b_fc1   = (const float*)d_in[19];
    const float* g_fc1   = (const float*)d_in[20];
    const float* be_fc1  = (const float*)d_in[21];
    const float* w_out   = (const float*)d_in[22];
    const float* b_out   = (const float*)d_in[23];
    float* out = (float*)d_out;

    // g_conv1 is zero here: module-load init on first call, tail kernel after.
    pfn_mom_kernel<<<dim3(MOMB, 3), 256>>>(sweep, map_pts, w_c1);          // 0 (+wT)
    pfn_fin_kernel<<<2, 64>>>(w_pfn_s, b_pfn_s, g_pfn_s, be_pfn_s,
                              w_pfn_m, b_pfn_m, g_pfn_m, be_pfn_m);        // 1
    pfn_max_kernel<<<dim3((Bn * Pn) / 16, 2), 256>>>(sweep, map_pts);      // 2

    sconv1_kernel<<<dim3(Bn * SC_CHUNKS, 4, 4), 128>>>();                  // 3 <- profiled slot

    pool1_kernel<<<P1GRID, 256>>>();                                       // 4 (pool + c1 stats)
    bn_fin_kernel<<<1, 64>>>(1, g_c1, be_c1, b_c1, 1.0 / ((double)Bn * OSZ1));

    conv2_kernel<<<dim3(5, 5, 16), 256>>>(w_c2);                           // ci-split x2
    pool2_kernel<<<Bn * 16, 256>>>();                                      // pool + c2 stats
    bn_fin_kernel<<<1, 32>>>(2, g_c2, be_c2, b_c2, 1.0 / ((double)Bn * OH2 * OH2));

    fc1_kernel<<<dim3(32, 4), 256>>>(w_fc1, b_fc1);
    head_kernel<<<1, 64>>>(g_fc1, be_fc1, w_out, b_out, out);

    // restore invariant: conv1 accumulator zero for next call/replay
    {
        size_t n4 = ((size_t)Bn * OSZ1 * 64) / 4;
        conv1_zero_kernel<<<(int)((n4 + 255) / 256), 256>>>();
    }
}